// round 1
// baseline (speedup 1.0000x reference)
#include <cuda_runtime.h>

// CrossCompressUnit: rank-1 cross compress.
// v_out = v * (e.w_vv) + e * (v.w_ev) + b_v
// e_out = v * (e.w_ve) + e * (v.w_ee) + b_e
// B = n rows, D = 128 fixed.
//
// One warp per row; lane l owns elements [4l, 4l+4). Four simultaneous
// warp-shuffle reductions. Weights cached in registers across the
// grid-stride row loop.

#define D 128

__global__ __launch_bounds__(256)
void cross_compress_kernel(const float* __restrict__ v,
                           const float* __restrict__ e,
                           const float* __restrict__ w_vv,
                           const float* __restrict__ w_ev,
                           const float* __restrict__ w_ve,
                           const float* __restrict__ w_ee,
                           const float* __restrict__ b_v,
                           const float* __restrict__ b_e,
                           float* __restrict__ out,   // [2*B*D]: v_out then e_out
                           int B)
{
    const int lane    = threadIdx.x & 31;
    const int warp_in_block = threadIdx.x >> 5;
    const int warps_per_block = blockDim.x >> 5;
    const int gwarp   = blockIdx.x * warps_per_block + warp_in_block;
    const int nwarps  = gridDim.x * warps_per_block;

    const int c = lane * 4;   // column base for this lane

    // Load per-lane weight slices once (L2/L1-resident, 3KB total).
    const float4 wvv = *reinterpret_cast<const float4*>(w_vv + c);
    const float4 wev = *reinterpret_cast<const float4*>(w_ev + c);
    const float4 wve = *reinterpret_cast<const float4*>(w_ve + c);
    const float4 wee = *reinterpret_cast<const float4*>(w_ee + c);
    const float4 bv  = *reinterpret_cast<const float4*>(b_v  + c);
    const float4 be  = *reinterpret_cast<const float4*>(b_e  + c);

    float* out_v = out;
    float* out_e = out + (size_t)B * D;

    for (int row = gwarp; row < B; row += nwarps) {
        const size_t base = (size_t)row * D + c;
        const float4 v4 = *reinterpret_cast<const float4*>(v + base);
        const float4 e4 = *reinterpret_cast<const float4*>(e + base);

        // Per-lane partial dot products.
        float p_vv = e4.x*wvv.x + e4.y*wvv.y + e4.z*wvv.z + e4.w*wvv.w; // e . w_vv
        float p_ev = v4.x*wev.x + v4.y*wev.y + v4.z*wev.z + v4.w*wev.w; // v . w_ev
        float p_ve = e4.x*wve.x + e4.y*wve.y + e4.z*wve.z + e4.w*wve.w; // e . w_ve
        float p_ee = v4.x*wee.x + v4.y*wee.y + v4.z*wee.z + v4.w*wee.w; // v . w_ee

        // Warp reduction (butterfly) on all four simultaneously.
        #pragma unroll
        for (int off = 16; off > 0; off >>= 1) {
            p_vv += __shfl_xor_sync(0xffffffffu, p_vv, off);
            p_ev += __shfl_xor_sync(0xffffffffu, p_ev, off);
            p_ve += __shfl_xor_sync(0xffffffffu, p_ve, off);
            p_ee += __shfl_xor_sync(0xffffffffu, p_ee, off);
        }

        float4 vo, eo;
        vo.x = v4.x * p_vv + e4.x * p_ev + bv.x;
        vo.y = v4.y * p_vv + e4.y * p_ev + bv.y;
        vo.z = v4.z * p_vv + e4.z * p_ev + bv.z;
        vo.w = v4.w * p_vv + e4.w * p_ev + bv.w;

        eo.x = v4.x * p_ve + e4.x * p_ee + be.x;
        eo.y = v4.y * p_ve + e4.y * p_ee + be.y;
        eo.z = v4.z * p_ve + e4.z * p_ee + be.z;
        eo.w = v4.w * p_ve + e4.w * p_ee + be.w;

        *reinterpret_cast<float4*>(out_v + base) = vo;
        *reinterpret_cast<float4*>(out_e + base) = eo;
    }
}

extern "C" void kernel_launch(void* const* d_in, const int* in_sizes, int n_in,
                              void* d_out, int out_size)
{
    const float* v    = (const float*)d_in[0];
    const float* e    = (const float*)d_in[1];
    const float* w_vv = (const float*)d_in[2];
    const float* w_ev = (const float*)d_in[3];
    const float* w_ve = (const float*)d_in[4];
    const float* w_ee = (const float*)d_in[5];
    const float* b_v  = (const float*)d_in[6];
    const float* b_e  = (const float*)d_in[7];
    float* out = (float*)d_out;

    const int B = in_sizes[0] / D;   // rows

    const int threads = 256;
    const int warps_per_block = threads / 32;
    // ~8 rows per warp; enough warps to saturate HBM.
    int blocks = (B + warps_per_block * 8 - 1) / (warps_per_block * 8);
    if (blocks < 1) blocks = 1;

    cross_compress_kernel<<<blocks, threads>>>(v, e, w_vv, w_ev, w_ve, w_ee,
                                               b_v, b_e, out, B);
}